// round 6
// baseline (speedup 1.0000x reference)
#include <cuda_runtime.h>

// Problem constants
#define B_    32
#define CIN_  64
#define Hh    32
#define Ww    32
#define CO_   64
#define KK    7
#define G_    8
#define PAD_  3
#define HP    38            // padded side
#define NPIX  (HP*HP)       // 1444

// Scratch (no cudaMalloc allowed)
__device__ float g_q[B_ * Hh * Ww * CO_];        // [b][hw][o]
__device__ float g_k[B_ * NPIX * CO_];           // [b][pp][o]
__device__ float g_v[B_ * NPIX * CO_];           // [b][pp][o]

// ---- packed fp32 helpers (sm_103a FFMA2 path) ------------------------------
#define PACKF(out, lo, hi) \
    asm("mov.b64 %0, {%1, %2};" : "=l"(out) : "f"(lo), "f"(hi))
#define UNPACKF(lo, hi, in) \
    asm("mov.b64 {%0, %1}, %2;" : "=f"(lo), "=f"(hi) : "l"(in))
#define FFMA2(d, a, b) \
    asm("fma.rn.f32x2 %0, %1, %2, %0;" : "+l"(d) : "l"(a), "l"(b))

// ---------------------------------------------------------------------------
// Fused Q/K/V projection over the padded 38x38 domain, single compute pass.
// CTA: 64 padded pixels, 256 threads. Thread = 2 px x 8 oc x 3 matrices
// (24 packed f32x2 accumulators). Weights transposed inline per CTA
// (scattered LDG is L1/L2-resident; STS coalesced).
// ---------------------------------------------------------------------------
__global__ __launch_bounds__(256) void proj_qkv_kernel(
    const float* __restrict__ x,
    const float* __restrict__ wq,
    const float* __restrict__ wk,
    const float* __restrict__ wv) {
    extern __shared__ float sm[];
    float* x_s = sm;            // [c][px] 64 x 64        (16 KB)
    float* w_s = sm + 4096;     // [m][c][o] 3 x 64 x 64  (48 KB)

    const int b  = blockIdx.y;
    const int p0 = blockIdx.x * 64;
    const float* xb = x + (size_t)b * (CIN_ * Hh * Ww);

    // transpose-fill weights: w_s[m][c][o] = W_m[o][c]
    for (int idx = threadIdx.x; idx < 12288; idx += 256) {
        int m = idx >> 12, r = idx & 4095;
        const float* W = (m == 0) ? wq : (m == 1 ? wk : wv);
        w_s[idx] = W[(r & 63) * 64 + (r >> 6)];
    }
    // fill x tile (zero outside image -> pad-then-project equivalence)
    for (int idx = threadIdx.x; idx < 4096; idx += 256) {
        int c = idx >> 6, px = idx & 63;
        int pp = p0 + px;
        float val = 0.f;
        if (pp < NPIX) {
            int y  = pp / HP;
            int xx = pp - y * HP;
            if (y >= PAD_ && y < PAD_ + Hh && xx >= PAD_ && xx < PAD_ + Ww)
                val = xb[c * 1024 + (y - PAD_) * Ww + (xx - PAD_)];
        }
        x_s[idx] = val;
    }
    __syncthreads();

    const int pxg = threadIdx.x & 31;   // 32 pixel-pairs
    const int ocg = threadIdx.x >> 5;   // 8 oc-groups
    const float2* x2 = (const float2*)x_s;          // 32 float2 per c-row
    // ulonglong2 view of w_s: 4 floats per element -> 16 per 64-float c-row,
    // 1024 per 4096-float matrix.
    const ulonglong2* w2 = (const ulonglong2*)w_s;

    unsigned long long acc[3][2][4];
#pragma unroll
    for (int m = 0; m < 3; m++)
#pragma unroll
        for (int p = 0; p < 2; p++)
#pragma unroll
            for (int j = 0; j < 4; j++) acc[m][p][j] = 0ULL;

#pragma unroll 8
    for (int c = 0; c < 64; c++) {
        float2 xv = x2[c * 32 + pxg];
        unsigned long long xp0, xp1;
        PACKF(xp0, xv.x, xv.x);
        PACKF(xp1, xv.y, xv.y);
#pragma unroll
        for (int m = 0; m < 3; m++) {
            ulonglong2 wa = w2[m * 1024 + c * 16 + ocg * 2];       // FIX m-stride
            ulonglong2 wb = w2[m * 1024 + c * 16 + ocg * 2 + 1];
            FFMA2(acc[m][0][0], xp0, wa.x); FFMA2(acc[m][0][1], xp0, wa.y);
            FFMA2(acc[m][0][2], xp0, wb.x); FFMA2(acc[m][0][3], xp0, wb.y);
            FFMA2(acc[m][1][0], xp1, wa.x); FFMA2(acc[m][1][1], xp1, wa.y);
            FFMA2(acc[m][1][2], xp1, wb.x); FFMA2(acc[m][1][3], xp1, wb.y);
        }
    }

#pragma unroll
    for (int p = 0; p < 2; p++) {
        int pix = p0 + pxg * 2 + p;
        if (pix >= NPIX) continue;
        int y  = pix / HP;
        int xx = pix - y * HP;
        bool interior = (y >= PAD_ && y < PAD_ + Hh && xx >= PAD_ && xx < PAD_ + Ww);
#pragma unroll
        for (int m = 0; m < 3; m++) {
            float o0, o1, o2, o3, o4, o5, o6, o7;
            UNPACKF(o0, o1, acc[m][p][0]);
            UNPACKF(o2, o3, acc[m][p][1]);
            UNPACKF(o4, o5, acc[m][p][2]);
            UNPACKF(o6, o7, acc[m][p][3]);
            float* op;
            if (m == 0) {
                if (!interior) continue;
                op = g_q + (size_t)(b * 1024 + (y - PAD_) * Ww + (xx - PAD_)) * 64 + ocg * 8;
            } else {
                float* dst = (m == 1) ? g_k : g_v;
                op = dst + (size_t)(b * NPIX + pix) * 64 + ocg * 8;
            }
            ((float4*)op)[0] = make_float4(o0, o1, o2, o3);
            ((float4*)op)[1] = make_float4(o4, o5, o6, o7);
        }
    }
}

// ---------------------------------------------------------------------------
// Attention: CTA = (b, g, 8-row tile). 128 threads, thread = 2 adjacent rows
// at one column (shares the 8x7 k/v window between the two rows).
// ---------------------------------------------------------------------------
#define TROWS 8
#define TPIX  532   // (TROWS + KK - 1) * HP = 14*38

__global__ __launch_bounds__(128) void attn_kernel(const float* __restrict__ rel_h,
                                                   const float* __restrict__ rel_w,
                                                   const float* __restrict__ cur,
                                                   float* __restrict__ out) {
    const int h0 = blockIdx.x * TROWS;
    const int g  = blockIdx.y;
    const int b  = blockIdx.z;

    __shared__ __align__(16) float k_s[2 * TPIX * 4];
    __shared__ __align__(16) float v_s[2 * TPIX * 4];
    float4* ks4 = (float4*)k_s;
    float4* vs4 = (float4*)v_s;

    const float4* gk4 = (const float4*)g_k + (size_t)(b * NPIX + h0 * HP) * 16 + g * 2;
    const float4* gv4 = (const float4*)g_v + (size_t)(b * NPIX + h0 * HP) * 16 + g * 2;
    for (int idx = threadIdx.x; idx < 2 * TPIX; idx += 128) {
        int pp = idx >> 1, c4 = idx & 1;
        ks4[c4 * TPIX + pp] = gk4[pp * 16 + c4];
        vs4[c4 * TPIX + pp] = gv4[pp * 16 + c4];
    }
    __syncthreads();

    const int rp = threadIdx.x >> 5;       // row-pair 0..3
    const int w  = threadIdx.x & 31;       // column
    const int hA = h0 + rp * 2;
    const int hB = hA + 1;

    const float4* qPA = (const float4*)(g_q + (size_t)(b * 1024 + hA * 32 + w) * 64 + g * 8);
    const float4* qPB = (const float4*)(g_q + (size_t)(b * 1024 + hB * 32 + w) * 64 + g * 8);
    float4 a0 = qPA[0], a1 = qPA[1];
    float4 b0 = qPB[0], b1 = qPB[1];
    float qA[8] = {a0.x, a0.y, a0.z, a0.w, a1.x, a1.y, a1.z, a1.w};
    float qB[8] = {b0.x, b0.y, b0.z, b0.w, b1.x, b1.y, b1.z, b1.w};
    unsigned long long qAp[4], qBp[4];
#pragma unroll
    for (int c = 0; c < 4; c++) {
        PACKF(qAp[c], qA[2 * c], qA[2 * c + 1]);
        PACKF(qBp[c], qB[2 * c], qB[2 * c + 1]);
    }

    // rel positional term: depends only on i (g<4) or j (g>=4)
    float relA[7], relB[7];
    {
        const float* rb = (g < 4) ? (rel_h + g * 56) : (rel_w + (g - 4) * 56);
#pragma unroll
        for (int t = 0; t < 7; t++) {
            float sA = 0.f, sB = 0.f;
#pragma unroll
            for (int c = 0; c < 8; c++) {
                float rv = rb[c * 7 + t];
                sA += qA[c] * rv;
                sB += qB[c] * rv;
            }
            relA[t] = sA; relB[t] = sB;
        }
    }

    const ulonglong2* ks2 = (const ulonglong2*)k_s;   // 1 u128 per smem pixel-record half
    const ulonglong2* vs2 = (const ulonglong2*)v_s;

    float scA[49], scB[49];
#pragma unroll
    for (int i = 0; i < 8; i++) {
        int rowbase = (rp * 2 + i) * HP + w;
#pragma unroll
        for (int j = 0; j < 7; j++) {
            int pix = rowbase + j;
            ulonglong2 ka = ks2[pix];
            ulonglong2 kb = ks2[TPIX + pix];
            if (i < 7) {
                unsigned long long t;
                PACKF(t, (g < 4) ? relA[i] : relA[j], 0.f);
                FFMA2(t, ka.x, qAp[0]); FFMA2(t, ka.y, qAp[1]);
                FFMA2(t, kb.x, qAp[2]); FFMA2(t, kb.y, qAp[3]);
                float lo, hi; UNPACKF(lo, hi, t);
                scA[i * 7 + j] = lo + hi;
            }
            if (i > 0) {
                unsigned long long t;
                PACKF(t, (g < 4) ? relB[i - 1] : relB[j], 0.f);
                FFMA2(t, ka.x, qBp[0]); FFMA2(t, ka.y, qBp[1]);
                FFMA2(t, kb.x, qBp[2]); FFMA2(t, kb.y, qBp[3]);
                float lo, hi; UNPACKF(lo, hi, t);
                scB[(i - 1) * 7 + j] = lo + hi;
            }
        }
    }

    // softmax per row
    float mA = scA[0], mB = scB[0];
#pragma unroll
    for (int s = 1; s < 49; s++) { mA = fmaxf(mA, scA[s]); mB = fmaxf(mB, scB[s]); }
    float sumA = 0.f, sumB = 0.f;
#pragma unroll
    for (int s = 0; s < 49; s++) {
        scA[s] = __expf(scA[s] - mA); sumA += scA[s];
        scB[s] = __expf(scB[s] - mB); sumB += scB[s];
    }

    unsigned long long oA[4] = {0, 0, 0, 0}, oB[4] = {0, 0, 0, 0};
#pragma unroll
    for (int i = 0; i < 8; i++) {
        int rowbase = (rp * 2 + i) * HP + w;
#pragma unroll
        for (int j = 0; j < 7; j++) {
            int pix = rowbase + j;
            ulonglong2 va = vs2[pix];
            ulonglong2 vb = vs2[TPIX + pix];
            if (i < 7) {
                float p = scA[i * 7 + j];
                unsigned long long pp; PACKF(pp, p, p);
                FFMA2(oA[0], pp, va.x); FFMA2(oA[1], pp, va.y);
                FFMA2(oA[2], pp, vb.x); FFMA2(oA[3], pp, vb.y);
            }
            if (i > 0) {
                float p = scB[(i - 1) * 7 + j];
                unsigned long long pp; PACKF(pp, p, p);
                FFMA2(oB[0], pp, va.x); FFMA2(oB[1], pp, va.y);
                FFMA2(oB[2], pp, vb.x); FFMA2(oB[3], pp, vb.y);
            }
        }
    }

    const float cg = cur[g];
    {
        float inv = 1.f / sumA;
        int rr = min(hA, 31 - hA);
        int lo = (hA <= 31 - hA) ? rr : rr + 1;
        int hi = 31 - rr;
        float om = ((float)(rr - 15) + cg * 16.f) / 3.f + 1.f;
        om = fminf(fmaxf(om, 0.f), 1.f);
        float mk = (w >= lo && w <= hi) ? om : 1.f;
        float scal = inv * mk;
        float o0, o1, o2, o3, o4, o5, o6, o7;
        UNPACKF(o0, o1, oA[0]); UNPACKF(o2, o3, oA[1]);
        UNPACKF(o4, o5, oA[2]); UNPACKF(o6, o7, oA[3]);
        float* op = out + (size_t)(b * 64 + g * 8) * 1024 + hA * 32 + w;
        op[0]        = o0 * scal; op[1024]     = o1 * scal;
        op[2 * 1024] = o2 * scal; op[3 * 1024] = o3 * scal;
        op[4 * 1024] = o4 * scal; op[5 * 1024] = o5 * scal;
        op[6 * 1024] = o6 * scal; op[7 * 1024] = o7 * scal;
    }
    {
        float inv = 1.f / sumB;
        int rr = min(hB, 31 - hB);
        int lo = (hB <= 31 - hB) ? rr : rr + 1;
        int hi = 31 - rr;
        float om = ((float)(rr - 15) + cg * 16.f) / 3.f + 1.f;
        om = fminf(fmaxf(om, 0.f), 1.f);
        float mk = (w >= lo && w <= hi) ? om : 1.f;
        float scal = inv * mk;
        float o0, o1, o2, o3, o4, o5, o6, o7;
        UNPACKF(o0, o1, oB[0]); UNPACKF(o2, o3, oB[1]);
        UNPACKF(o4, o5, oB[2]); UNPACKF(o6, o7, oB[3]);
        float* op = out + (size_t)(b * 64 + g * 8) * 1024 + hB * 32 + w;
        op[0]        = o0 * scal; op[1024]     = o1 * scal;
        op[2 * 1024] = o2 * scal; op[3 * 1024] = o3 * scal;
        op[4 * 1024] = o4 * scal; op[5 * 1024] = o5 * scal;
        op[6 * 1024] = o6 * scal; op[7 * 1024] = o7 * scal;
    }
}

// ---------------------------------------------------------------------------
extern "C" void kernel_launch(void* const* d_in, const int* in_sizes, int n_in,
                              void* d_out, int out_size) {
    const float* x  = (const float*)d_in[0];
    const float* wq = (const float*)d_in[1];
    const float* wk = (const float*)d_in[2];
    const float* wv = (const float*)d_in[3];
    const float* rh = (const float*)d_in[4];
    const float* rw = (const float*)d_in[5];
    const float* cv = (const float*)d_in[6];
    float* out = (float*)d_out;

    // Not a stream op; safe to call every launch (no static guards allowed).
    cudaFuncSetAttribute(proj_qkv_kernel,
                         cudaFuncAttributeMaxDynamicSharedMemorySize, 65536);

    proj_qkv_kernel<<<dim3(23, B_), 256, 65536>>>(x, wq, wk, wv);
    attn_kernel<<<dim3(Hh / TROWS, G_, B_), 128>>>(rh, rw, cv, out);
}

// round 7
// speedup vs baseline: 1.3377x; 1.3377x over previous
#include <cuda_runtime.h>

// Problem constants
#define B_    32
#define CIN_  64
#define Hh    32
#define Ww    32
#define CO_   64
#define KK    7
#define G_    8
#define PAD_  3
#define HP    38            // padded side
#define NPIX  (HP*HP)       // 1444

// Scratch (no cudaMalloc allowed)
__device__ float g_q[B_ * Hh * Ww * CO_];        // [b][hw][o]
__device__ float g_k[B_ * NPIX * CO_];           // [b][pp][o]
__device__ float g_v[B_ * NPIX * CO_];           // [b][pp][o]
__device__ float g_wT[3 * CIN_ * CO_];           // [m][c][o]

// ---- packed fp32 helpers (sm_103a FFMA2 path) ------------------------------
#define PACKF(out, lo, hi) \
    asm("mov.b64 %0, {%1, %2};" : "=l"(out) : "f"(lo), "f"(hi))
#define UNPACKF(lo, hi, in) \
    asm("mov.b64 {%0, %1}, %2;" : "=f"(lo), "=f"(hi) : "l"(in))
#define FFMA2(d, a, b) \
    asm("fma.rn.f32x2 %0, %1, %2, %0;" : "+l"(d) : "l"(a), "l"(b))

// ---------------------------------------------------------------------------
// Transpose weights (o,c) -> (c,o). grid=24 x 512 threads: 12288 elements,
// one element per thread -> ~1.5us (launch-latency bound).
// ---------------------------------------------------------------------------
__global__ __launch_bounds__(512) void transpose_w_kernel(
    const float* __restrict__ wq,
    const float* __restrict__ wk,
    const float* __restrict__ wv) {
    int idx = blockIdx.x * 512 + threadIdx.x;    // 0..12287
    int m = idx >> 12, r = idx & 4095;
    const float* W = (m == 0) ? wq : (m == 1 ? wk : wv);
    // dst[m][c][o] = W[o][c];  r = c*64+o
    g_wT[idx] = W[(r & 63) * 64 + (r >> 6)];
}

// ---------------------------------------------------------------------------
// Fused Q/K/V projection over the padded 38x38 domain. 3 passes over a
// shared x tile; weights (pre-transposed) reloaded per pass (coalesced).
// CTA: 128 padded pixels, 256 threads. Thread = 4 px x 8 oc, packed f32x2.
// ---------------------------------------------------------------------------
__global__ __launch_bounds__(256) void proj_qkv_kernel(const float* __restrict__ x) {
    __shared__ __align__(16) float x_s[8192];   // [c][px] 64 x 128 (32 KB)
    __shared__ __align__(16) float w_s[4096];   // [c][o]           (16 KB)

    const int b  = blockIdx.y;
    const int p0 = blockIdx.x * 128;
    const float* xb = x + (size_t)b * (CIN_ * Hh * Ww);

    // fill x tile (zero outside image -> pad-then-project equivalence)
    for (int idx = threadIdx.x; idx < 8192; idx += 256) {
        int c = idx >> 7, px = idx & 127;
        int pp = p0 + px;
        float val = 0.f;
        if (pp < NPIX) {
            int y  = pp / HP;
            int xx = pp - y * HP;
            if (y >= PAD_ && y < PAD_ + Hh && xx >= PAD_ && xx < PAD_ + Ww)
                val = xb[c * 1024 + (y - PAD_) * Ww + (xx - PAD_)];
        }
        x_s[idx] = val;
    }

    const int pxg = threadIdx.x & 31;   // 32 groups of 4 pixels
    const int ocg = threadIdx.x >> 5;   // 8 groups of 8 out-ch
    const float4* x4 = (const float4*)x_s;          // 32 float4 per 128-px c-row
    const ulonglong2* w2 = (const ulonglong2*)w_s;  // 16 u128 per 64-f c-row

    for (int m = 0; m < 3; m++) {
        __syncthreads();   // protect w_s reuse (also covers x_s fill on m=0)
        for (int idx = threadIdx.x; idx < 4096; idx += 256)
            w_s[idx] = g_wT[m * 4096 + idx];
        __syncthreads();

        unsigned long long acc[4][4];   // [px][oc-pair]
#pragma unroll
        for (int p = 0; p < 4; p++)
#pragma unroll
            for (int j = 0; j < 4; j++) acc[p][j] = 0ULL;

#pragma unroll 8
        for (int c = 0; c < 64; c++) {
            float4 xv = x4[c * 32 + pxg];
            ulonglong2 wa = w2[c * 16 + ocg * 2];
            ulonglong2 wb = w2[c * 16 + ocg * 2 + 1];
            float xs[4] = {xv.x, xv.y, xv.z, xv.w};
#pragma unroll
            for (int p = 0; p < 4; p++) {
                unsigned long long xp;
                PACKF(xp, xs[p], xs[p]);
                FFMA2(acc[p][0], xp, wa.x);
                FFMA2(acc[p][1], xp, wa.y);
                FFMA2(acc[p][2], xp, wb.x);
                FFMA2(acc[p][3], xp, wb.y);
            }
        }

#pragma unroll
        for (int p = 0; p < 4; p++) {
            int pix = p0 + pxg * 4 + p;
            if (pix >= NPIX) continue;
            float o0, o1, o2, o3, o4, o5, o6, o7;
            UNPACKF(o0, o1, acc[p][0]);
            UNPACKF(o2, o3, acc[p][1]);
            UNPACKF(o4, o5, acc[p][2]);
            UNPACKF(o6, o7, acc[p][3]);
            float* op;
            if (m == 0) {
                int y  = pix / HP;
                int xx = pix - y * HP;
                if (y < PAD_ || y >= PAD_ + Hh || xx < PAD_ || xx >= PAD_ + Ww) continue;
                op = g_q + (size_t)(b * 1024 + (y - PAD_) * Ww + (xx - PAD_)) * 64 + ocg * 8;
            } else {
                float* dst = (m == 1) ? g_k : g_v;
                op = dst + (size_t)(b * NPIX + pix) * 64 + ocg * 8;
            }
            ((float4*)op)[0] = make_float4(o0, o1, o2, o3);
            ((float4*)op)[1] = make_float4(o4, o5, o6, o7);
        }
    }
}

// ---------------------------------------------------------------------------
// Attention: CTA = (b, g, 8-row tile). 256 threads, thread = ONE pixel
// (R1 shape — best occupancy), packed f32x2 for channel dots/accumulation.
// ---------------------------------------------------------------------------
#define TROWS 8
#define TPIX  532   // (TROWS + KK - 1) * HP = 14*38

__global__ __launch_bounds__(256) void attn_kernel(const float* __restrict__ rel_h,
                                                   const float* __restrict__ rel_w,
                                                   const float* __restrict__ cur,
                                                   float* __restrict__ out) {
    const int h0 = blockIdx.x * TROWS;
    const int g  = blockIdx.y;
    const int b  = blockIdx.z;

    __shared__ __align__(16) float k_s[2 * TPIX * 4];
    __shared__ __align__(16) float v_s[2 * TPIX * 4];
    float4* ks4 = (float4*)k_s;
    float4* vs4 = (float4*)v_s;

    const float4* gk4 = (const float4*)g_k + (size_t)(b * NPIX + h0 * HP) * 16 + g * 2;
    const float4* gv4 = (const float4*)g_v + (size_t)(b * NPIX + h0 * HP) * 16 + g * 2;
    for (int idx = threadIdx.x; idx < 2 * TPIX; idx += 256) {
        int pp = idx >> 1, c4 = idx & 1;
        ks4[c4 * TPIX + pp] = gk4[pp * 16 + c4];
        vs4[c4 * TPIX + pp] = gv4[pp * 16 + c4];
    }
    __syncthreads();

    const int r = threadIdx.x >> 5;        // local row
    const int w = threadIdx.x & 31;        // column
    const int h = h0 + r;

    const float4* qp = (const float4*)(g_q + (size_t)(b * 1024 + h * 32 + w) * 64 + g * 8);
    float4 qa = qp[0], qb = qp[1];
    float q[8] = {qa.x, qa.y, qa.z, qa.w, qb.x, qb.y, qb.z, qb.w};
    unsigned long long qpk[4];
#pragma unroll
    for (int c = 0; c < 4; c++) PACKF(qpk[c], q[2 * c], q[2 * c + 1]);

    // rel positional term: depends only on i (g<4) or j (g>=4)
    float rel[7];
    {
        const float* rb = (g < 4) ? (rel_h + g * 56) : (rel_w + (g - 4) * 56);
#pragma unroll
        for (int t = 0; t < 7; t++) {
            float s = 0.f;
#pragma unroll
            for (int c = 0; c < 8; c++) s += q[c] * rb[c * 7 + t];
            rel[t] = s;
        }
    }

    const ulonglong2* ks2 = (const ulonglong2*)k_s;   // u128 per smem pixel half
    const ulonglong2* vs2 = (const ulonglong2*)v_s;

    float sc[49];
#pragma unroll
    for (int i = 0; i < 7; i++) {
        int base = (r + i) * HP + w;
#pragma unroll
        for (int j = 0; j < 7; j++) {
            int pix = base + j;
            ulonglong2 ka = ks2[pix];
            ulonglong2 kb = ks2[TPIX + pix];
            unsigned long long t;
            PACKF(t, (g < 4) ? rel[i] : rel[j], 0.f);
            FFMA2(t, ka.x, qpk[0]); FFMA2(t, ka.y, qpk[1]);
            FFMA2(t, kb.x, qpk[2]); FFMA2(t, kb.y, qpk[3]);
            float lo, hi; UNPACKF(lo, hi, t);
            sc[i * 7 + j] = lo + hi;
        }
    }

    // softmax over 49
    float m = sc[0];
#pragma unroll
    for (int s = 1; s < 49; s++) m = fmaxf(m, sc[s]);
    float sum = 0.f;
#pragma unroll
    for (int s = 0; s < 49; s++) { sc[s] = __expf(sc[s] - m); sum += sc[s]; }

    unsigned long long oa[4] = {0, 0, 0, 0};
#pragma unroll
    for (int i = 0; i < 7; i++) {
        int base = (r + i) * HP + w;
#pragma unroll
        for (int j = 0; j < 7; j++) {
            int pix = base + j;
            float p = sc[i * 7 + j];
            unsigned long long pp; PACKF(pp, p, p);
            ulonglong2 va = vs2[pix];
            ulonglong2 vb = vs2[TPIX + pix];
            FFMA2(oa[0], pp, va.x); FFMA2(oa[1], pp, va.y);
            FFMA2(oa[2], pp, vb.x); FFMA2(oa[3], pp, vb.y);
        }
    }

    float inv = 1.f / sum;

    // adaptive ring mask
    int rr = min(h, 31 - h);
    int lo = (h <= 31 - h) ? rr : rr + 1;
    int hi = 31 - rr;
    float om = ((float)(rr - 15) + cur[g] * 16.f) / 3.f + 1.f;
    om = fminf(fmaxf(om, 0.f), 1.f);
    float mk = (w >= lo && w <= hi) ? om : 1.f;
    float scal = inv * mk;

    float o0, o1, o2, o3, o4, o5, o6, o7;
    UNPACKF(o0, o1, oa[0]); UNPACKF(o2, o3, oa[1]);
    UNPACKF(o4, o5, oa[2]); UNPACKF(o6, o7, oa[3]);
    float* op = out + (size_t)(b * 64 + g * 8) * 1024 + h * 32 + w;
    op[0]        = o0 * scal; op[1024]     = o1 * scal;
    op[2 * 1024] = o2 * scal; op[3 * 1024] = o3 * scal;
    op[4 * 1024] = o4 * scal; op[5 * 1024] = o5 * scal;
    op[6 * 1024] = o6 * scal; op[7 * 1024] = o7 * scal;
}

// ---------------------------------------------------------------------------
extern "C" void kernel_launch(void* const* d_in, const int* in_sizes, int n_in,
                              void* d_out, int out_size) {
    const float* x  = (const float*)d_in[0];
    const float* wq = (const float*)d_in[1];
    const float* wk = (const float*)d_in[2];
    const float* wv = (const float*)d_in[3];
    const float* rh = (const float*)d_in[4];
    const float* rw = (const float*)d_in[5];
    const float* cv = (const float*)d_in[6];
    float* out = (float*)d_out;

    transpose_w_kernel<<<24, 512>>>(wq, wk, wv);
    proj_qkv_kernel<<<dim3(12, B_), 256>>>(x);
    attn_kernel<<<dim3(Hh / TROWS, G_, B_), 256>>>(rh, rw, cv, out);
}

// round 8
// speedup vs baseline: 1.5382x; 1.1499x over previous
#include <cuda_runtime.h>

// Problem constants
#define B_    32
#define CIN_  64
#define Hh    32
#define Ww    32
#define CO_   64
#define KK    7
#define G_    8
#define PAD_  3
#define HP    38            // padded side
#define NPIX  (HP*HP)       // 1444

// Scratch (no cudaMalloc allowed)
__device__ float g_q[B_ * Hh * Ww * CO_];        // [b][hw][o]
__device__ float g_k[B_ * NPIX * CO_];           // [b][pp][o]
__device__ float g_v[B_ * NPIX * CO_];           // [b][pp][o]
__device__ float g_wT[3 * CIN_ * CO_];           // [m][c][o]

// ---- packed fp32 helpers (sm_103a FFMA2 path) ------------------------------
#define PACKF(out, lo, hi) \
    asm("mov.b64 %0, {%1, %2};" : "=l"(out) : "f"(lo), "f"(hi))
#define UNPACKF(lo, hi, in) \
    asm("mov.b64 {%0, %1}, %2;" : "=f"(lo), "=f"(hi) : "l"(in))
#define FFMA2(d, a, b) \
    asm("fma.rn.f32x2 %0, %1, %2, %0;" : "+l"(d) : "l"(a), "l"(b))

// ---------------------------------------------------------------------------
// Utility kernel: blocks 0..23 transpose weights (o,c)->(c,o);
// blocks 24.. zero the k/v border records (pad-projection of zero = zero).
// ---------------------------------------------------------------------------
#define UTIL_TW_BLOCKS  24
#define UTIL_BLOCKS     600
__global__ __launch_bounds__(512) void util_kernel(
    const float* __restrict__ wq,
    const float* __restrict__ wk,
    const float* __restrict__ wv) {
    if (blockIdx.x < UTIL_TW_BLOCKS) {
        int idx = blockIdx.x * 512 + threadIdx.x;    // 0..12287
        int m = idx >> 12, r = idx & 4095;
        const float* W = (m == 0) ? wq : (m == 1 ? wk : wv);
        g_wT[idx] = W[(r & 63) * 64 + (r >> 6)];     // dst[m][c][o]=W[o][c]
        return;
    }
    // border zero: iterate (b, pp, c4) over b*NPIX*16 float4 slots
    const int total  = B_ * NPIX * 16;               // 739328
    const int stride = (UTIL_BLOCKS - UTIL_TW_BLOCKS) * 512;
    float4 z = make_float4(0.f, 0.f, 0.f, 0.f);
    float4* k4 = (float4*)g_k;
    float4* v4 = (float4*)g_v;
    for (int i = (blockIdx.x - UTIL_TW_BLOCKS) * 512 + threadIdx.x;
         i < total; i += stride) {
        int pp = (i >> 4) % NPIX;
        int y  = pp / HP;
        int xx = pp - y * HP;
        bool interior = (y >= PAD_ && y < PAD_ + Hh && xx >= PAD_ && xx < PAD_ + Ww);
        if (!interior) { k4[i] = z; v4[i] = z; }
    }
}

// ---------------------------------------------------------------------------
// Fused Q/K/V projection, INTERIOR pixels only (borders are zero, handled by
// util_kernel). CTA = 128 contiguous image pixels, 256 threads.
// Smem: x tile 32KB + all three transposed weights 48KB (dynamic, 80KB).
// Three sequential m-passes share the x tile; no syncs between passes.
// Thread = 4 px x 8 oc, packed f32x2 accumulators (32 regs live per pass).
// ---------------------------------------------------------------------------
__global__ __launch_bounds__(256) void proj_qkv_kernel(const float* __restrict__ x) {
    extern __shared__ float sm[];
    float* x_s = sm;            // [c][px]     64 x 128  (32 KB)
    float* w_s = sm + 8192;     // [m][c][o]  3 x 64 x 64 (48 KB)

    const int b  = blockIdx.y;
    const int p0 = blockIdx.x * 128;                 // interior pixel base
    const float* xb = x + (size_t)b * (CIN_ * Hh * Ww);

    for (int idx = threadIdx.x; idx < 8192; idx += 256) {
        int c = idx >> 7, px = idx & 127;
        x_s[idx] = xb[c * 1024 + p0 + px];           // contiguous, coalesced
    }
    for (int idx = threadIdx.x; idx < 12288; idx += 256)
        w_s[idx] = g_wT[idx];
    __syncthreads();

    const int pxg = threadIdx.x & 31;   // 32 groups of 4 pixels
    const int ocg = threadIdx.x >> 5;   // 8 groups of 8 out-ch
    const float4* x4 = (const float4*)x_s;          // 32 float4 per c-row
    // ulonglong2 view of w_s: 16 per 64-float c-row, 1024 per 4096-f matrix
    const ulonglong2* w2 = (const ulonglong2*)w_s;

#pragma unroll
    for (int m = 0; m < 3; m++) {
        unsigned long long acc[4][4];   // [px][oc-pair]
#pragma unroll
        for (int p = 0; p < 4; p++)
#pragma unroll
            for (int j = 0; j < 4; j++) acc[p][j] = 0ULL;

#pragma unroll 8
        for (int c = 0; c < 64; c++) {
            float4 xv = x4[c * 32 + pxg];
            ulonglong2 wa = w2[m * 1024 + c * 16 + ocg * 2];
            ulonglong2 wb = w2[m * 1024 + c * 16 + ocg * 2 + 1];
            float xs[4] = {xv.x, xv.y, xv.z, xv.w};
#pragma unroll
            for (int p = 0; p < 4; p++) {
                unsigned long long xp;
                PACKF(xp, xs[p], xs[p]);
                FFMA2(acc[p][0], xp, wa.x);
                FFMA2(acc[p][1], xp, wa.y);
                FFMA2(acc[p][2], xp, wb.x);
                FFMA2(acc[p][3], xp, wb.y);
            }
        }

#pragma unroll
        for (int p = 0; p < 4; p++) {
            int pix = p0 + pxg * 4 + p;              // image index 0..1023
            float o0, o1, o2, o3, o4, o5, o6, o7;
            UNPACKF(o0, o1, acc[p][0]);
            UNPACKF(o2, o3, acc[p][1]);
            UNPACKF(o4, o5, acc[p][2]);
            UNPACKF(o6, o7, acc[p][3]);
            float* op;
            if (m == 0) {
                op = g_q + (size_t)(b * 1024 + pix) * 64 + ocg * 8;
            } else {
                // padded coordinate for k/v
                int pp = ((pix >> 5) + PAD_) * HP + (pix & 31) + PAD_;
                float* dst = (m == 1) ? g_k : g_v;
                op = dst + (size_t)(b * NPIX + pp) * 64 + ocg * 8;
            }
            ((float4*)op)[0] = make_float4(o0, o1, o2, o3);
            ((float4*)op)[1] = make_float4(o4, o5, o6, o7);
        }
    }
}

// ---------------------------------------------------------------------------
// Attention: CTA = (b, g, 8-row tile). 256 threads, thread = one pixel,
// packed f32x2 for channel dots/accumulation.
// ---------------------------------------------------------------------------
#define TROWS 8
#define TPIX  532   // (TROWS + KK - 1) * HP = 14*38

__global__ __launch_bounds__(256) void attn_kernel(const float* __restrict__ rel_h,
                                                   const float* __restrict__ rel_w,
                                                   const float* __restrict__ cur,
                                                   float* __restrict__ out) {
    const int h0 = blockIdx.x * TROWS;
    const int g  = blockIdx.y;
    const int b  = blockIdx.z;

    __shared__ __align__(16) float k_s[2 * TPIX * 4];
    __shared__ __align__(16) float v_s[2 * TPIX * 4];
    float4* ks4 = (float4*)k_s;
    float4* vs4 = (float4*)v_s;

    const float4* gk4 = (const float4*)g_k + (size_t)(b * NPIX + h0 * HP) * 16 + g * 2;
    const float4* gv4 = (const float4*)g_v + (size_t)(b * NPIX + h0 * HP) * 16 + g * 2;
    for (int idx = threadIdx.x; idx < 2 * TPIX; idx += 256) {
        int pp = idx >> 1, c4 = idx & 1;
        ks4[c4 * TPIX + pp] = gk4[pp * 16 + c4];
        vs4[c4 * TPIX + pp] = gv4[pp * 16 + c4];
    }
    __syncthreads();

    const int r = threadIdx.x >> 5;        // local row
    const int w = threadIdx.x & 31;        // column
    const int h = h0 + r;

    const float4* qp = (const float4*)(g_q + (size_t)(b * 1024 + h * 32 + w) * 64 + g * 8);
    float4 qa = qp[0], qb = qp[1];
    float q[8] = {qa.x, qa.y, qa.z, qa.w, qb.x, qb.y, qb.z, qb.w};
    unsigned long long qpk[4];
#pragma unroll
    for (int c = 0; c < 4; c++) PACKF(qpk[c], q[2 * c], q[2 * c + 1]);

    // rel positional term: depends only on i (g<4) or j (g>=4)
    float rel[7];
    {
        const float* rb = (g < 4) ? (rel_h + g * 56) : (rel_w + (g - 4) * 56);
#pragma unroll
        for (int t = 0; t < 7; t++) {
            float s = 0.f;
#pragma unroll
            for (int c = 0; c < 8; c++) s += q[c] * rb[c * 7 + t];
            rel[t] = s;
        }
    }

    const ulonglong2* ks2 = (const ulonglong2*)k_s;
    const ulonglong2* vs2 = (const ulonglong2*)v_s;

    float sc[49];
#pragma unroll
    for (int i = 0; i < 7; i++) {
        int base = (r + i) * HP + w;
#pragma unroll
        for (int j = 0; j < 7; j++) {
            int pix = base + j;
            ulonglong2 ka = ks2[pix];
            ulonglong2 kb = ks2[TPIX + pix];
            unsigned long long t;
            PACKF(t, (g < 4) ? rel[i] : rel[j], 0.f);
            FFMA2(t, ka.x, qpk[0]); FFMA2(t, ka.y, qpk[1]);
            FFMA2(t, kb.x, qpk[2]); FFMA2(t, kb.y, qpk[3]);
            float lo, hi; UNPACKF(lo, hi, t);
            sc[i * 7 + j] = lo + hi;
        }
    }

    // softmax over 49
    float m = sc[0];
#pragma unroll
    for (int s = 1; s < 49; s++) m = fmaxf(m, sc[s]);
    float sum = 0.f;
#pragma unroll
    for (int s = 0; s < 49; s++) { sc[s] = __expf(sc[s] - m); sum += sc[s]; }

    unsigned long long oa[4] = {0, 0, 0, 0};
#pragma unroll
    for (int i = 0; i < 7; i++) {
        int base = (r + i) * HP + w;
#pragma unroll
        for (int j = 0; j < 7; j++) {
            int pix = base + j;
            float p = sc[i * 7 + j];
            unsigned long long pp; PACKF(pp, p, p);
            ulonglong2 va = vs2[pix];
            ulonglong2 vb = vs2[TPIX + pix];
            FFMA2(oa[0], pp, va.x); FFMA2(oa[1], pp, va.y);
            FFMA2(oa[2], pp, vb.x); FFMA2(oa[3], pp, vb.y);
        }
    }

    float inv = 1.f / sum;

    // adaptive ring mask
    int rr = min(h, 31 - h);
    int lo = (h <= 31 - h) ? rr : rr + 1;
    int hi = 31 - rr;
    float om = ((float)(rr - 15) + cur[g] * 16.f) / 3.f + 1.f;
    om = fminf(fmaxf(om, 0.f), 1.f);
    float mk = (w >= lo && w <= hi) ? om : 1.f;
    float scal = inv * mk;

    float o0, o1, o2, o3, o4, o5, o6, o7;
    UNPACKF(o0, o1, oa[0]); UNPACKF(o2, o3, oa[1]);
    UNPACKF(o4, o5, oa[2]); UNPACKF(o6, o7, oa[3]);
    float* op = out + (size_t)(b * 64 + g * 8) * 1024 + h * 32 + w;
    op[0]        = o0 * scal; op[1024]     = o1 * scal;
    op[2 * 1024] = o2 * scal; op[3 * 1024] = o3 * scal;
    op[4 * 1024] = o4 * scal; op[5 * 1024] = o5 * scal;
    op[6 * 1024] = o6 * scal; op[7 * 1024] = o7 * scal;
}

// ---------------------------------------------------------------------------
extern "C" void kernel_launch(void* const* d_in, const int* in_sizes, int n_in,
                              void* d_out, int out_size) {
    const float* x  = (const float*)d_in[0];
    const float* wq = (const float*)d_in[1];
    const float* wk = (const float*)d_in[2];
    const float* wv = (const float*)d_in[3];
    const float* rh = (const float*)d_in[4];
    const float* rw = (const float*)d_in[5];
    const float* cv = (const float*)d_in[6];
    float* out = (float*)d_out;

    // Not a stream op; safe to call every launch.
    cudaFuncSetAttribute(proj_qkv_kernel,
                         cudaFuncAttributeMaxDynamicSharedMemorySize, 81920);

    util_kernel<<<UTIL_BLOCKS, 512>>>(wq, wk, wv);
    proj_qkv_kernel<<<dim3(8, B_), 256, 81920>>>(x);
    attn_kernel<<<dim3(Hh / TROWS, G_, B_), 256>>>(rh, rw, cv, out);
}

// round 11
// speedup vs baseline: 1.8723x; 1.2172x over previous
#include <cuda_runtime.h>
#include <cuda_bf16.h>
#include <cstdint>

// Problem constants
#define B_    32
#define CIN_  64
#define Hh    32
#define Ww    32
#define CO_   64
#define KK    7
#define G_    8
#define PAD_  3
#define HP    38            // padded side
#define NPIX  (HP*HP)       // 1444

// Scratch (no cudaMalloc allowed)
__device__ float g_q[B_ * Hh * Ww * CO_];        // [b][hw][o]
__device__ float g_k[B_ * NPIX * CO_];           // [b][pp][o]
__device__ float g_v[B_ * NPIX * CO_];           // [b][pp][o]
// bf16 split weights, packed pairs: [n=m*64+oc][c2] (u32 = 2 bf16 along c)
__device__ uint32_t g_wh[3 * CO_ * 32];
__device__ uint32_t g_wl[3 * CO_ * 32];

// ---- packed fp32 helpers (attention kernel) --------------------------------
#define PACKF(out, lo, hi) \
    asm("mov.b64 %0, {%1, %2};" : "=l"(out) : "f"(lo), "f"(hi))
#define UNPACKF(lo, hi, in) \
    asm("mov.b64 {%0, %1}, %2;" : "=f"(lo), "=f"(hi) : "l"(in))
#define FFMA2(d, a, b) \
    asm("fma.rn.f32x2 %0, %1, %2, %0;" : "+l"(d) : "l"(a), "l"(b))

// ---- bf16 HMMA m16n8k16 (sm_80+ path, works on plain sm_103 target) --------
__device__ __forceinline__ void mma16816(float* d, const uint32_t* a,
                                         uint32_t b0, uint32_t b1) {
    asm volatile(
        "mma.sync.aligned.m16n8k16.row.col.f32.bf16.bf16.f32 "
        "{%0,%1,%2,%3}, {%4,%5,%6,%7}, {%8,%9}, {%0,%1,%2,%3};"
        : "+f"(d[0]), "+f"(d[1]), "+f"(d[2]), "+f"(d[3])
        : "r"(a[0]), "r"(a[1]), "r"(a[2]), "r"(a[3]), "r"(b0), "r"(b1));
}

__device__ __forceinline__ uint32_t pack_bf16_hi(float x0, float x1,
                                                 float& r0, float& r1) {
    __nv_bfloat16 h0 = __float2bfloat16(x0);
    __nv_bfloat16 h1 = __float2bfloat16(x1);
    r0 = x0 - __bfloat162float(h0);
    r1 = x1 - __bfloat162float(h1);
    return ((uint32_t)__bfloat16_as_ushort(h1) << 16) | __bfloat16_as_ushort(h0);
}
__device__ __forceinline__ uint32_t pack_bf16(float x0, float x1) {
    return ((uint32_t)__bfloat16_as_ushort(__float2bfloat16(x1)) << 16) |
           __bfloat16_as_ushort(__float2bfloat16(x0));
}

// ---------------------------------------------------------------------------
// Util: blocks 0..11 split weights into packed bf16 hi/lo pairs [n][c2];
// blocks 12.. zero k/v border records (pad-projection of zero = zero).
// ---------------------------------------------------------------------------
#define UTIL_TW_BLOCKS  12
#define UTIL_BLOCKS     600
__global__ __launch_bounds__(512) void util_kernel(
    const float* __restrict__ wq,
    const float* __restrict__ wk,
    const float* __restrict__ wv) {
    if (blockIdx.x < UTIL_TW_BLOCKS) {
        int idx = blockIdx.x * 512 + threadIdx.x;    // 0..6143: n*32+c2
        int n = idx >> 5, c2 = idx & 31;
        int m = n >> 6, oc = n & 63;
        const float* W = (m == 0) ? wq : (m == 1 ? wk : wv);
        float v0 = W[oc * 64 + 2 * c2];
        float v1 = W[oc * 64 + 2 * c2 + 1];
        float r0, r1;
        g_wh[idx] = pack_bf16_hi(v0, v1, r0, r1);
        g_wl[idx] = pack_bf16(r0, r1);
        return;
    }
    const int total  = B_ * NPIX * 16;               // float4 slots
    const int stride = (UTIL_BLOCKS - UTIL_TW_BLOCKS) * 512;
    float4 z = make_float4(0.f, 0.f, 0.f, 0.f);
    float4* k4 = (float4*)g_k;
    float4* v4 = (float4*)g_v;
    for (int i = (blockIdx.x - UTIL_TW_BLOCKS) * 512 + threadIdx.x;
         i < total; i += stride) {
        int pp = (i >> 4) % NPIX;
        int y  = pp / HP;
        int xx = pp - y * HP;
        bool interior = (y >= PAD_ && y < PAD_ + Hh && xx >= PAD_ && xx < PAD_ + Ww);
        if (!interior) { k4[i] = z; v4[i] = z; }
    }
}

// ---------------------------------------------------------------------------
// HMMA projection: CTA = 128 interior pixels of one batch, 256 threads.
// D[128,192] = Xsplit[128,64] x Wsplit[64,192], 3 bf16 products, fp32 acc.
// Smem rows padded to 72 bf16 (36 u32) -> conflict-free fragment loads.
// Warp w owns M rows [16w,16w+16); loops m(3) x ntile(8) x ktile(4).
// ---------------------------------------------------------------------------
#define SA      36                       // row stride in u32 (72 bf16)
#define A_PLANE (128 * SA)               // u32 count = 4608 (18432 B)
#define B_PLANE (192 * SA)               // u32 count = 6912 (27648 B)
#define OFF_AH  0
#define OFF_AL  (A_PLANE)
#define OFF_BH  (2 * A_PLANE)
#define OFF_BL  (2 * A_PLANE + B_PLANE)
#define SMEM_TC ((2 * A_PLANE + 2 * B_PLANE) * 4)   // 92160 bytes

__global__ __launch_bounds__(256) void proj_tc_kernel(const float* __restrict__ x) {
    extern __shared__ uint32_t sm32[];
    const int tid = threadIdx.x;
    const int b   = blockIdx.x >> 3;
    const int p0  = (blockIdx.x & 7) * 128;          // interior pixel base

    // A fill: x fp32 -> bf16 hi/lo pairs (pair along c), [px][c2]
    const float* xb = x + (size_t)b * 65536;
    for (int i = tid; i < 4096; i += 256) {
        int px = i & 127, c2 = i >> 7;               // c2 = channel pair 0..31
        float x0 = xb[(2 * c2) * 1024 + p0 + px];
        float x1 = xb[(2 * c2 + 1) * 1024 + p0 + px];
        float r0, r1;
        sm32[OFF_AH + px * SA + c2] = pack_bf16_hi(x0, x1, r0, r1);
        sm32[OFF_AL + px * SA + c2] = pack_bf16(r0, r1);
    }
    // B fill: pre-split weights [n][c2]
    for (int i = tid; i < 6144; i += 256) {
        int n = i >> 5, c2 = i & 31;
        sm32[OFF_BH + n * SA + c2] = g_wh[i];
        sm32[OFF_BL + n * SA + c2] = g_wl[i];
    }
    __syncthreads();

    const int w   = tid >> 5;            // warp 0..7 -> M-tile
    const int t   = tid & 31;
    const int qid = t >> 2;              // 0..7
    const int q4  = t & 3;               // 0..3

    // A fragments for all 4 k-tiles, hi+lo planes (32 regs)
    uint32_t ah[4][4], al[4][4];
    {
        int r0 = 16 * w + qid;
#pragma unroll
        for (int kt = 0; kt < 4; kt++) {
            int cidx = kt * 8 + q4;      // u32 col index of pair
            ah[kt][0] = sm32[OFF_AH + r0 * SA + cidx];
            ah[kt][1] = sm32[OFF_AH + (r0 + 8) * SA + cidx];
            ah[kt][2] = sm32[OFF_AH + r0 * SA + cidx + 4];
            ah[kt][3] = sm32[OFF_AH + (r0 + 8) * SA + cidx + 4];
            al[kt][0] = sm32[OFF_AL + r0 * SA + cidx];
            al[kt][1] = sm32[OFF_AL + (r0 + 8) * SA + cidx];
            al[kt][2] = sm32[OFF_AL + r0 * SA + cidx + 4];
            al[kt][3] = sm32[OFF_AL + (r0 + 8) * SA + cidx + 4];
        }
    }

    const int pixA = p0 + 16 * w + qid;
    const int pixB = pixA + 8;
    const int ppA  = ((pixA >> 5) + PAD_) * HP + (pixA & 31) + PAD_;
    const int ppB  = ((pixB >> 5) + PAD_) * HP + (pixB & 31) + PAD_;

#pragma unroll
    for (int m = 0; m < 3; m++) {
        float d[8][4];
#pragma unroll
        for (int nt = 0; nt < 8; nt++)
#pragma unroll
            for (int j = 0; j < 4; j++) d[nt][j] = 0.f;

#pragma unroll
        for (int kt = 0; kt < 4; kt++) {
            int cidx = kt * 8 + q4;
#pragma unroll
            for (int nt = 0; nt < 8; nt++) {
                int n0 = m * 64 + nt * 8 + qid;
                uint32_t bh0 = sm32[OFF_BH + n0 * SA + cidx];
                uint32_t bh1 = sm32[OFF_BH + n0 * SA + cidx + 4];
                uint32_t bl0 = sm32[OFF_BL + n0 * SA + cidx];
                uint32_t bl1 = sm32[OFF_BL + n0 * SA + cidx + 4];
                mma16816(d[nt], ah[kt], bh0, bh1);   // xh*wh
                mma16816(d[nt], ah[kt], bl0, bl1);   // xh*wl
                mma16816(d[nt], al[kt], bh0, bh1);   // xl*wh
            }
        }

        // epilogue: thread writes rows pixA (d0,d1) and pixB (d2,d3)
        float* baseA;
        float* baseB;
        if (m == 0) {
            baseA = g_q + (size_t)(b * 1024 + pixA) * 64;
            baseB = g_q + (size_t)(b * 1024 + pixB) * 64;
        } else {
            float* dst = (m == 1) ? g_k : g_v;
            baseA = dst + (size_t)(b * NPIX + ppA) * 64;
            baseB = dst + (size_t)(b * NPIX + ppB) * 64;
        }
#pragma unroll
        for (int nt = 0; nt < 8; nt++) {
            int c = nt * 8 + q4 * 2;
            *(float2*)(baseA + c) = make_float2(d[nt][0], d[nt][1]);
            *(float2*)(baseB + c) = make_float2(d[nt][2], d[nt][3]);
        }
    }
}

// ---------------------------------------------------------------------------
// Attention: CTA = (b, g, 8-row tile). 256 threads, thread = one pixel,
// packed f32x2 for channel dots/accumulation. (unchanged from R8)
// ---------------------------------------------------------------------------
#define TROWS 8
#define TPIX  532   // (TROWS + KK - 1) * HP

__global__ __launch_bounds__(256) void attn_kernel(const float* __restrict__ rel_h,
                                                   const float* __restrict__ rel_w,
                                                   const float* __restrict__ cur,
                                                   float* __restrict__ out) {
    const int h0 = blockIdx.x * TROWS;
    const int g  = blockIdx.y;
    const int b  = blockIdx.z;

    __shared__ __align__(16) float k_s[2 * TPIX * 4];
    __shared__ __align__(16) float v_s[2 * TPIX * 4];
    float4* ks4 = (float4*)k_s;
    float4* vs4 = (float4*)v_s;

    const float4* gk4 = (const float4*)g_k + (size_t)(b * NPIX + h0 * HP) * 16 + g * 2;
    const float4* gv4 = (const float4*)g_v + (size_t)(b * NPIX + h0 * HP) * 16 + g * 2;
    for (int idx = threadIdx.x; idx < 2 * TPIX; idx += 256) {
        int pp = idx >> 1, c4 = idx & 1;
        ks4[c4 * TPIX + pp] = gk4[pp * 16 + c4];
        vs4[c4 * TPIX + pp] = gv4[pp * 16 + c4];
    }
    __syncthreads();

    const int r = threadIdx.x >> 5;
    const int w = threadIdx.x & 31;
    const int h = h0 + r;

    const float4* qp = (const float4*)(g_q + (size_t)(b * 1024 + h * 32 + w) * 64 + g * 8);
    float4 qa = qp[0], qb = qp[1];
    float q[8] = {qa.x, qa.y, qa.z, qa.w, qb.x, qb.y, qb.z, qb.w};
    unsigned long long qpk[4];
#pragma unroll
    for (int c = 0; c < 4; c++) PACKF(qpk[c], q[2 * c], q[2 * c + 1]);

    float rel[7];
    {
        const float* rb = (g < 4) ? (rel_h + g * 56) : (rel_w + (g - 4) * 56);
#pragma unroll
        for (int t = 0; t < 7; t++) {
            float s = 0.f;
#pragma unroll
            for (int c = 0; c < 8; c++) s += q[c] * rb[c * 7 + t];
            rel[t] = s;
        }
    }

    const ulonglong2* ks2 = (const ulonglong2*)k_s;
    const ulonglong2* vs2 = (const ulonglong2*)v_s;

    float sc[49];
#pragma unroll
    for (int i = 0; i < 7; i++) {
        int base = (r + i) * HP + w;
#pragma unroll
        for (int j = 0; j < 7; j++) {
            int pix = base + j;
            ulonglong2 ka = ks2[pix];
            ulonglong2 kb = ks2[TPIX + pix];
            unsigned long long t;
            PACKF(t, (g < 4) ? rel[i] : rel[j], 0.f);
            FFMA2(t, ka.x, qpk[0]); FFMA2(t, ka.y, qpk[1]);
            FFMA2(t, kb.x, qpk[2]); FFMA2(t, kb.y, qpk[3]);
            float lo, hi; UNPACKF(lo, hi, t);
            sc[i * 7 + j] = lo + hi;
        }
    }

    float m = sc[0];
#pragma unroll
    for (int s = 1; s < 49; s++) m = fmaxf(m, sc[s]);
    float sum = 0.f;
#pragma unroll
    for (int s = 0; s < 49; s++) { sc[s] = __expf(sc[s] - m); sum += sc[s]; }

    unsigned long long oa[4] = {0, 0, 0, 0};
#pragma unroll
    for (int i = 0; i < 7; i++) {
        int base = (r + i) * HP + w;
#pragma unroll
        for (int j = 0; j < 7; j++) {
            int pix = base + j;
            float p = sc[i * 7 + j];
            unsigned long long pp; PACKF(pp, p, p);
            ulonglong2 va = vs2[pix];
            ulonglong2 vb = vs2[TPIX + pix];
            FFMA2(oa[0], pp, va.x); FFMA2(oa[1], pp, va.y);
            FFMA2(oa[2], pp, vb.x); FFMA2(oa[3], pp, vb.y);
        }
    }

    float inv = 1.f / sum;
    int rr = min(h, 31 - h);
    int lo = (h <= 31 - h) ? rr : rr + 1;
    int hi = 31 - rr;
    float om = ((float)(rr - 15) + cur[g] * 16.f) / 3.f + 1.f;
    om = fminf(fmaxf(om, 0.f), 1.f);
    float mk = (w >= lo && w <= hi) ? om : 1.f;
    float scal = inv * mk;

    float o0, o1, o2, o3, o4, o5, o6, o7;
    UNPACKF(o0, o1, oa[0]); UNPACKF(o2, o3, oa[1]);
    UNPACKF(o4, o5, oa[2]); UNPACKF(o6, o7, oa[3]);
    float* op = out + (size_t)(b * 64 + g * 8) * 1024 + h * 32 + w;
    op[0]        = o0 * scal; op[1024]     = o1 * scal;
    op[2 * 1024] = o2 * scal; op[3 * 1024] = o3 * scal;
    op[4 * 1024] = o4 * scal; op[5 * 1024] = o5 * scal;
    op[6 * 1024] = o6 * scal; op[7 * 1024] = o7 * scal;
}

// ---------------------------------------------------------------------------
extern "C" void kernel_launch(void* const* d_in, const int* in_sizes, int n_in,
                              void* d_out, int out_size) {
    const float* x  = (const float*)d_in[0];
    const float* wq = (const float*)d_in[1];
    const float* wk = (const float*)d_in[2];
    const float* wv = (const float*)d_in[3];
    const float* rh = (const float*)d_in[4];
    const float* rw = (const float*)d_in[5];
    const float* cv = (const float*)d_in[6];
    float* out = (float*)d_out;

    cudaFuncSetAttribute(proj_tc_kernel,
                         cudaFuncAttributeMaxDynamicSharedMemorySize, SMEM_TC);

    util_kernel<<<UTIL_BLOCKS, 512>>>(wq, wk, wv);
    proj_tc_kernel<<<256, 256, SMEM_TC>>>(x);
    attn_kernel<<<dim3(Hh / TROWS, G_, B_), 256>>>(rh, rw, cv, out);
}

// round 12
// speedup vs baseline: 1.8917x; 1.0104x over previous
#include <cuda_runtime.h>
#include <cuda_bf16.h>
#include <cstdint>

// Problem constants
#define B_    32
#define CIN_  64
#define Hh    32
#define Ww    32
#define CO_   64
#define KK    7
#define G_    8
#define PAD_  3
#define HP    38            // padded side
#define NPIX  (HP*HP)       // 1444

// Scratch (no cudaMalloc allowed)
__device__ float g_q[B_ * Hh * Ww * CO_];        // [b][hw][o]
__device__ float g_k[B_ * NPIX * CO_];           // [b][pp][o]
__device__ float g_v[B_ * NPIX * CO_];           // [b][pp][o]
// bf16 split weights, packed pairs: [n=m*64+oc][c2] (u32 = 2 bf16 along c)
__device__ uint32_t g_wh[3 * CO_ * 32];
__device__ uint32_t g_wl[3 * CO_ * 32];

// ---- packed fp32 helpers (attention kernel) --------------------------------
#define PACKF(out, lo, hi) \
    asm("mov.b64 %0, {%1, %2};" : "=l"(out) : "f"(lo), "f"(hi))
#define UNPACKF(lo, hi, in) \
    asm("mov.b64 {%0, %1}, %2;" : "=f"(lo), "=f"(hi) : "l"(in))
#define FFMA2(d, a, b) \
    asm("fma.rn.f32x2 %0, %1, %2, %0;" : "+l"(d) : "l"(a), "l"(b))

// ---- bf16 HMMA m16n8k16 ----------------------------------------------------
__device__ __forceinline__ void mma16816(float* d, const uint32_t* a,
                                         uint32_t b0, uint32_t b1) {
    asm volatile(
        "mma.sync.aligned.m16n8k16.row.col.f32.bf16.bf16.f32 "
        "{%0,%1,%2,%3}, {%4,%5,%6,%7}, {%8,%9}, {%0,%1,%2,%3};"
        : "+f"(d[0]), "+f"(d[1]), "+f"(d[2]), "+f"(d[3])
        : "r"(a[0]), "r"(a[1]), "r"(a[2]), "r"(a[3]), "r"(b0), "r"(b1));
}

__device__ __forceinline__ uint32_t pack_bf16_hi(float x0, float x1,
                                                 float& r0, float& r1) {
    __nv_bfloat16 h0 = __float2bfloat16(x0);
    __nv_bfloat16 h1 = __float2bfloat16(x1);
    r0 = x0 - __bfloat162float(h0);
    r1 = x1 - __bfloat162float(h1);
    return ((uint32_t)__bfloat16_as_ushort(h1) << 16) | __bfloat16_as_ushort(h0);
}
__device__ __forceinline__ uint32_t pack_bf16(float x0, float x1) {
    return ((uint32_t)__bfloat16_as_ushort(__float2bfloat16(x1)) << 16) |
           __bfloat16_as_ushort(__float2bfloat16(x0));
}

// ---------------------------------------------------------------------------
// Util: blocks 0..11 split weights into packed bf16 hi/lo pairs [n][c2];
// blocks 12.. zero ONLY the 420 border pixel records per batch (k and v).
// ---------------------------------------------------------------------------
#define UTIL_TW_BLOCKS  12
#define NBORDER         420                       // 1444 - 1024
#define UTIL_BLOCKS     (UTIL_TW_BLOCKS + (B_ * NBORDER * 16 + 511) / 512)  // 432
__global__ __launch_bounds__(512) void util_kernel(
    const float* __restrict__ wq,
    const float* __restrict__ wk,
    const float* __restrict__ wv) {
    if (blockIdx.x < UTIL_TW_BLOCKS) {
        int idx = blockIdx.x * 512 + threadIdx.x;    // 0..6143: n*32+c2
        int n = idx >> 5, c2 = idx & 31;
        int m = n >> 6, oc = n & 63;
        const float* W = (m == 0) ? wq : (m == 1 ? wk : wv);
        float v0 = W[oc * 64 + 2 * c2];
        float v1 = W[oc * 64 + 2 * c2 + 1];
        float r0, r1;
        g_wh[idx] = pack_bf16_hi(v0, v1, r0, r1);
        g_wl[idx] = pack_bf16(r0, r1);
        return;
    }
    const int i = (blockIdx.x - UTIL_TW_BLOCKS) * 512 + threadIdx.x;
    const int total = B_ * NBORDER * 16;             // 215040 float4 slots
    if (i >= total) return;
    int c4 = i & 15;
    int r  = i >> 4;
    int bj = r % NBORDER;
    int b  = r / NBORDER;
    int pp;
    if (bj < 114)       pp = bj;                     // rows 0..2
    else if (bj < 228)  pp = 1330 + (bj - 114);      // rows 35..37
    else {                                           // middle rows, side cols
        int t2  = bj - 228;                          // 0..191
        int row = t2 / 6;
        int cc  = t2 - row * 6;                      // 0..5
        pp = (row + PAD_) * HP + (cc < 3 ? cc : cc + 32);
    }
    size_t slot = (((size_t)(b * NPIX + pp)) << 4) | c4;
    float4 z = make_float4(0.f, 0.f, 0.f, 0.f);
    ((float4*)g_k)[slot] = z;
    ((float4*)g_v)[slot] = z;
}

// ---------------------------------------------------------------------------
// HMMA projection: CTA = 128 interior pixels of one batch, 256 threads.
// D[128,192] = Xsplit[128,64] x Wsplit[64,192], 3 bf16 products, fp32 acc.
// A: rows padded to 36 u32 (qid row-delta 36 = 4 mod 32 -> conflict-free).
// B: rows of 32 u32 with column rotation (c2 + 4*(n&7)) & 31 -> fragment
//    loads hit banks {4*qid + q4} = all distinct -> conflict-free.
// ---------------------------------------------------------------------------
#define SA      36                        // A row stride in u32
#define A_PLANE (128 * SA)                // 4608 u32
#define BROW    32                        // B row stride in u32
#define B_PLANE (192 * BROW)              // 6144 u32
#define OFF_AH  0
#define OFF_AL  (A_PLANE)
#define OFF_BH  (2 * A_PLANE)
#define OFF_BL  (2 * A_PLANE + B_PLANE)
#define SMEM_TC ((2 * A_PLANE + 2 * B_PLANE) * 4)   // 86016 bytes

__global__ __launch_bounds__(256) void proj_tc_kernel(const float* __restrict__ x) {
    extern __shared__ uint32_t sm32[];
    const int tid = threadIdx.x;
    const int b   = blockIdx.x >> 3;
    const int p0  = (blockIdx.x & 7) * 128;          // interior pixel base

    // A fill: x fp32 -> bf16 hi/lo pairs (pair along c), [px][c2]
    const float* xb = x + (size_t)b * 65536;
    for (int i = tid; i < 4096; i += 256) {
        int px = i & 127, c2 = i >> 7;               // c2 = channel pair 0..31
        float x0 = xb[(2 * c2) * 1024 + p0 + px];
        float x1 = xb[(2 * c2 + 1) * 1024 + p0 + px];
        float r0, r1;
        sm32[OFF_AH + px * SA + c2] = pack_bf16_hi(x0, x1, r0, r1);
        sm32[OFF_AL + px * SA + c2] = pack_bf16(r0, r1);
    }
    // B fill: pre-split weights [n][c2], column-rotated by 4*(n&7)
    for (int i = tid; i < 6144; i += 256) {
        int n = i >> 5, c2 = i & 31;
        int sc = (c2 + 4 * (n & 7)) & 31;
        sm32[OFF_BH + n * BROW + sc] = g_wh[i];
        sm32[OFF_BL + n * BROW + sc] = g_wl[i];
    }
    __syncthreads();

    const int w   = tid >> 5;            // warp 0..7 -> M-tile
    const int t   = tid & 31;
    const int qid = t >> 2;              // 0..7
    const int q4  = t & 3;               // 0..3

    // A fragments for all 4 k-tiles, hi+lo planes (32 regs)
    uint32_t ah[4][4], al[4][4];
    {
        int r0 = 16 * w + qid;
#pragma unroll
        for (int kt = 0; kt < 4; kt++) {
            int cidx = kt * 8 + q4;      // u32 col index of pair
            ah[kt][0] = sm32[OFF_AH + r0 * SA + cidx];
            ah[kt][1] = sm32[OFF_AH + (r0 + 8) * SA + cidx];
            ah[kt][2] = sm32[OFF_AH + r0 * SA + cidx + 4];
            ah[kt][3] = sm32[OFF_AH + (r0 + 8) * SA + cidx + 4];
            al[kt][0] = sm32[OFF_AL + r0 * SA + cidx];
            al[kt][1] = sm32[OFF_AL + (r0 + 8) * SA + cidx];
            al[kt][2] = sm32[OFF_AL + r0 * SA + cidx + 4];
            al[kt][3] = sm32[OFF_AL + (r0 + 8) * SA + cidx + 4];
        }
    }

    const int pixA = p0 + 16 * w + qid;
    const int pixB = pixA + 8;
    const int ppA  = ((pixA >> 5) + PAD_) * HP + (pixA & 31) + PAD_;
    const int ppB  = ((pixB >> 5) + PAD_) * HP + (pixB & 31) + PAD_;
    const int rot  = 4 * qid;            // B column rotation for this thread

#pragma unroll
    for (int m = 0; m < 3; m++) {
        float d[8][4];
#pragma unroll
        for (int nt = 0; nt < 8; nt++)
#pragma unroll
            for (int j = 0; j < 4; j++) d[nt][j] = 0.f;

#pragma unroll
        for (int kt = 0; kt < 4; kt++) {
            int c0 = kt * 8 + q4;
            int s0 = (c0 + rot) & 31;
            int s1 = (c0 + 4 + rot) & 31;
#pragma unroll
            for (int nt = 0; nt < 8; nt++) {
                int nb = (m * 64 + nt * 8 + qid) * BROW;
                uint32_t bh0 = sm32[OFF_BH + nb + s0];
                uint32_t bh1 = sm32[OFF_BH + nb + s1];
                uint32_t bl0 = sm32[OFF_BL + nb + s0];
                uint32_t bl1 = sm32[OFF_BL + nb + s1];
                mma16816(d[nt], ah[kt], bh0, bh1);   // xh*wh
                mma16816(d[nt], ah[kt], bl0, bl1);   // xh*wl
                mma16816(d[nt], al[kt], bh0, bh1);   // xl*wh
            }
        }

        // epilogue: thread writes rows pixA (d0,d1) and pixB (d2,d3)
        float* baseA;
        float* baseB;
        if (m == 0) {
            baseA = g_q + (size_t)(b * 1024 + pixA) * 64;
            baseB = g_q + (size_t)(b * 1024 + pixB) * 64;
        } else {
            float* dst = (m == 1) ? g_k : g_v;
            baseA = dst + (size_t)(b * NPIX + ppA) * 64;
            baseB = dst + (size_t)(b * NPIX + ppB) * 64;
        }
#pragma unroll
        for (int nt = 0; nt < 8; nt++) {
            int c = nt * 8 + q4 * 2;
            *(float2*)(baseA + c) = make_float2(d[nt][0], d[nt][1]);
            *(float2*)(baseB + c) = make_float2(d[nt][2], d[nt][3]);
        }
    }
}

// ---------------------------------------------------------------------------
// Attention: CTA = (b, g, 8-row tile). 256 threads, thread = one pixel,
// packed f32x2 for channel dots/accumulation. (unchanged)
// ---------------------------------------------------------------------------
#define TROWS 8
#define TPIX  532   // (TROWS + KK - 1) * HP

__global__ __launch_bounds__(256) void attn_kernel(const float* __restrict__ rel_h,
                                                   const float* __restrict__ rel_w,
                                                   const float* __restrict__ cur,
                                                   float* __restrict__ out) {
    const int h0 = blockIdx.x * TROWS;
    const int g  = blockIdx.y;
    const int b  = blockIdx.z;

    __shared__ __align__(16) float k_s[2 * TPIX * 4];
    __shared__ __align__(16) float v_s[2 * TPIX * 4];
    float4* ks4 = (float4*)k_s;
    float4* vs4 = (float4*)v_s;

    const float4* gk4 = (const float4*)g_k + (size_t)(b * NPIX + h0 * HP) * 16 + g * 2;
    const float4* gv4 = (const float4*)g_v + (size_t)(b * NPIX + h0 * HP) * 16 + g * 2;
    for (int idx = threadIdx.x; idx < 2 * TPIX; idx += 256) {
        int pp = idx >> 1, c4 = idx & 1;
        ks4[c4 * TPIX + pp] = gk4[pp * 16 + c4];
        vs4[c4 * TPIX + pp] = gv4[pp * 16 + c4];
    }
    __syncthreads();

    const int r = threadIdx.x >> 5;
    const int w = threadIdx.x & 31;
    const int h = h0 + r;

    const float4* qp = (const float4*)(g_q + (size_t)(b * 1024 + h * 32 + w) * 64 + g * 8);
    float4 qa = qp[0], qb = qp[1];
    float q[8] = {qa.x, qa.y, qa.z, qa.w, qb.x, qb.y, qb.z, qb.w};
    unsigned long long qpk[4];
#pragma unroll
    for (int c = 0; c < 4; c++) PACKF(qpk[c], q[2 * c], q[2 * c + 1]);

    float rel[7];
    {
        const float* rb = (g < 4) ? (rel_h + g * 56) : (rel_w + (g - 4) * 56);
#pragma unroll
        for (int t = 0; t < 7; t++) {
            float s = 0.f;
#pragma unroll
            for (int c = 0; c < 8; c++) s += q[c] * rb[c * 7 + t];
            rel[t] = s;
        }
    }

    const ulonglong2* ks2 = (const ulonglong2*)k_s;
    const ulonglong2* vs2 = (const ulonglong2*)v_s;

    float sc[49];
#pragma unroll
    for (int i = 0; i < 7; i++) {
        int base = (r + i) * HP + w;
#pragma unroll
        for (int j = 0; j < 7; j++) {
            int pix = base + j;
            ulonglong2 ka = ks2[pix];
            ulonglong2 kb = ks2[TPIX + pix];
            unsigned long long t;
            PACKF(t, (g < 4) ? rel[i] : rel[j], 0.f);
            FFMA2(t, ka.x, qpk[0]); FFMA2(t, ka.y, qpk[1]);
            FFMA2(t, kb.x, qpk[2]); FFMA2(t, kb.y, qpk[3]);
            float lo, hi; UNPACKF(lo, hi, t);
            sc[i * 7 + j] = lo + hi;
        }
    }

    float m = sc[0];
#pragma unroll
    for (int s = 1; s < 49; s++) m = fmaxf(m, sc[s]);
    float sum = 0.f;
#pragma unroll
    for (int s = 0; s < 49; s++) { sc[s] = __expf(sc[s] - m); sum += sc[s]; }

    unsigned long long oa[4] = {0, 0, 0, 0};
#pragma unroll
    for (int i = 0; i < 7; i++) {
        int base = (r + i) * HP + w;
#pragma unroll
        for (int j = 0; j < 7; j++) {
            int pix = base + j;
            float p = sc[i * 7 + j];
            unsigned long long pp; PACKF(pp, p, p);
            ulonglong2 va = vs2[pix];
            ulonglong2 vb = vs2[TPIX + pix];
            FFMA2(oa[0], pp, va.x); FFMA2(oa[1], pp, va.y);
            FFMA2(oa[2], pp, vb.x); FFMA2(oa[3], pp, vb.y);
        }
    }

    float inv = 1.f / sum;
    int rr = min(h, 31 - h);
    int lo = (h <= 31 - h) ? rr : rr + 1;
    int hi = 31 - rr;
    float om = ((float)(rr - 15) + cur[g] * 16.f) / 3.f + 1.f;
    om = fminf(fmaxf(om, 0.f), 1.f);
    float mk = (w >= lo && w <= hi) ? om : 1.f;
    float scal = inv * mk;

    float o0, o1, o2, o3, o4, o5, o6, o7;
    UNPACKF(o0, o1, oa[0]); UNPACKF(o2, o3, oa[1]);
    UNPACKF(o4, o5, oa[2]); UNPACKF(o6, o7, oa[3]);
    float* op = out + (size_t)(b * 64 + g * 8) * 1024 + h * 32 + w;
    op[0]        = o0 * scal; op[1024]     = o1 * scal;
    op[2 * 1024] = o2 * scal; op[3 * 1024] = o3 * scal;
    op[4 * 1024] = o4 * scal; op[5 * 1024] = o5 * scal;
    op[6 * 1024] = o6 * scal; op[7 * 1024] = o7 * scal;
}

// ---------------------------------------------------------------------------
extern "C" void kernel_launch(void* const* d_in, const int* in_sizes, int n_in,
                              void* d_out, int out_size) {
    const float* x  = (const float*)d_in[0];
    const float* wq = (const float*)d_in[1];
    const float* wk = (const float*)d_in[2];
    const float* wv = (const float*)d_in[3];
    const float* rh = (const float*)d_in[4];
    const float* rw = (const float*)d_in[5];
    const float* cv = (const float*)d_in[6];
    float* out = (float*)d_out;

    cudaFuncSetAttribute(proj_tc_kernel,
                         cudaFuncAttributeMaxDynamicSharedMemorySize, SMEM_TC);

    util_kernel<<<UTIL_BLOCKS, 512>>>(wq, wk, wv);
    proj_tc_kernel<<<256, 256, SMEM_TC>>>(x);
    attn_kernel<<<dim3(Hh / TROWS, G_, B_), 256>>>(rh, rw, cv, out);
}